// round 4
// baseline (speedup 1.0000x reference)
#include <cuda_runtime.h>
#include <math.h>

// Problem constants
#define RAYS_C   2048
#define SS       128          // samples per ray
#define HID      256          // hidden width
#define XPAD     100          // X feature row stride (99 features + pad, mult of 4)
#define HPAD     260          // hidden activation row stride (mult of 4)
#define KT       32           // K tile for weight streaming
#define NTHREADS 512

// Shared memory layout (in floats)
#define SX_OFF    0            // 128*100   = 12800
#define SH_OFF    12800        // 128*260   = 33280
#define SW_OFF    46080        // 32*256    = 8192
#define SW4_OFF   54272        // 256*5     = 1280
#define SOUTS_OFF 55552        // 128*4     = 512
#define SSIG_OFF  56064        // 128
#define SBW_OFF   56192        // 128
#define SRGB_OFF  56320        // 384
#define SZ_OFF    56704        // 128
#define SWGT_OFF  56832        // 128
#define SMEM_FLOATS 56960      // 227840 bytes

struct MLPParams {
    const float* W[5];
    const float* b[5];
};

__device__ __forceinline__ float sigmoidf_(float x) {
    return 1.0f / (1.0f + expf(-x));
}

// C[128,256] = relu_or_id( A[128,K] @ W[K,256] + b ), written back transposed-layout
// A: smem, row-major [m][k] with stride apad. Out: smem row-major [m][n] stride HPAD.
// In-place (Hout == A) is safe: accumulators live in registers; writeback is after a barrier.
__device__ __forceinline__ void gemm_hidden(
    const float* __restrict__ A, int apad, int Kpad, int Kreal,
    const float* __restrict__ gW, const float* __restrict__ gB,
    float* __restrict__ sW, float* __restrict__ Hout)
{
    const int tid = threadIdx.x;
    const int tm  = tid >> 5;   // warp id 0..15  -> rows {tm*4..+3} and {64+tm*4..+3}
    const int tn  = tid & 31;   // lane          -> cols {tn*4..+3} and {128+tn*4..+3}

    float acc[8][8];
    {
        float bj[8];
#pragma unroll
        for (int j = 0; j < 4; j++) {
            bj[j]     = __ldg(gB + tn * 4 + j);
            bj[4 + j] = __ldg(gB + 128 + tn * 4 + j);
        }
#pragma unroll
        for (int i = 0; i < 8; i++)
#pragma unroll
            for (int j = 0; j < 8; j++) acc[i][j] = bj[j];
    }

    const float* arow0 = A + (tm * 4) * apad;
    const float* arow1 = A + (64 + tm * 4) * apad;

    for (int kbase = 0; kbase < Kpad; kbase += KT) {
        const int ktc = min(KT, Kpad - kbase);   // multiple of 4 by construction
        __syncthreads();  // prior compute done reading sW (and prior writeback visible)
        // Stream weight tile rows [kbase, kbase+ktc) into smem; zero-fill rows >= Kreal.
        {
            const int nf4 = ktc * (HID / 4);
            const float4* gsrc = reinterpret_cast<const float4*>(gW + kbase * HID);
            float4* dst = reinterpret_cast<float4*>(sW);
            for (int idx = tid; idx < nf4; idx += NTHREADS) {
                const int gk = kbase + (idx >> 6);
                float4 v;
                if (gk < Kreal) v = __ldg(gsrc + idx);
                else            v = make_float4(0.f, 0.f, 0.f, 0.f);
                dst[idx] = v;
            }
        }
        __syncthreads();

        for (int k = 0; k < ktc; k += 4) {
            float4 a[8];
#pragma unroll
            for (int i = 0; i < 4; i++) {
                a[i]     = *reinterpret_cast<const float4*>(arow0 + i * apad + kbase + k);
                a[4 + i] = *reinterpret_cast<const float4*>(arow1 + i * apad + kbase + k);
            }
#pragma unroll
            for (int kk = 0; kk < 4; kk++) {
                const float4 wlo = *reinterpret_cast<const float4*>(sW + (k + kk) * HID + tn * 4);
                const float4 whi = *reinterpret_cast<const float4*>(sW + (k + kk) * HID + 128 + tn * 4);
#pragma unroll
                for (int i = 0; i < 8; i++) {
                    const float av = (kk == 0) ? a[i].x : (kk == 1) ? a[i].y
                                   : (kk == 2) ? a[i].z : a[i].w;
                    acc[i][0] += av * wlo.x; acc[i][1] += av * wlo.y;
                    acc[i][2] += av * wlo.z; acc[i][3] += av * wlo.w;
                    acc[i][4] += av * whi.x; acc[i][5] += av * whi.y;
                    acc[i][6] += av * whi.z; acc[i][7] += av * whi.w;
                }
            }
        }
    }
    __syncthreads();  // all threads finished reading A before (possibly aliased) writeback

#pragma unroll
    for (int i = 0; i < 8; i++) {
        const int row = (i < 4) ? (tm * 4 + i) : (64 + tm * 4 + (i - 4));
        float4 v0, v1;
        v0.x = fmaxf(acc[i][0], 0.f); v0.y = fmaxf(acc[i][1], 0.f);
        v0.z = fmaxf(acc[i][2], 0.f); v0.w = fmaxf(acc[i][3], 0.f);
        v1.x = fmaxf(acc[i][4], 0.f); v1.y = fmaxf(acc[i][5], 0.f);
        v1.z = fmaxf(acc[i][6], 0.f); v1.w = fmaxf(acc[i][7], 0.f);
        *reinterpret_cast<float4*>(Hout + row * HPAD + tn * 4)       = v0;
        *reinterpret_cast<float4*>(Hout + row * HPAD + 128 + tn * 4) = v1;
    }
}

// 4 hidden layers (layer 0 reads sX). Shared once between the two MLPs to keep I$ small.
__device__ __noinline__ void run_mlp4(
    const float* const* W, const float* const* b,
    const float* sX, int Kpad0, int Kreal0, float* sH, float* sW)
{
    for (int l = 0; l < 4; l++) {
        const float* A   = (l == 0) ? sX   : sH;
        const int   apad = (l == 0) ? XPAD : HPAD;
        const int   Kp   = (l == 0) ? Kpad0 : HID;
        const int   Kr   = (l == 0) ? Kreal0 : HID;
        gemm_hidden(A, apad, Kp, Kr, W[l], b[l], sW, sH);
    }
}

// Last layer: out[m][j] = sH[m,:] @ W[256,NOUT] + b, NOUT in {4,5}. tid<128 active.
template <int NOUT>
__device__ __forceinline__ void final_layer(
    const float* __restrict__ sH, const float* __restrict__ gW,
    const float* __restrict__ gB, float* __restrict__ sW4, float out[NOUT])
{
    const int tid = threadIdx.x;
    for (int idx = tid; idx < HID * NOUT; idx += NTHREADS) sW4[idx] = __ldg(gW + idx);
    __syncthreads();
    if (tid < SS) {
#pragma unroll
        for (int j = 0; j < NOUT; j++) out[j] = __ldg(gB + j);
        const float* arow = sH + tid * HPAD;
        for (int k = 0; k < HID; k += 4) {
            const float4 a = *reinterpret_cast<const float4*>(arow + k);
#pragma unroll
            for (int kk = 0; kk < 4; kk++) {
                const float av = (kk == 0) ? a.x : (kk == 1) ? a.y : (kk == 2) ? a.z : a.w;
#pragma unroll
                for (int j = 0; j < NOUT; j++) out[j] += av * sW4[(k + kk) * NOUT + j];
            }
        }
    }
    __syncthreads();  // reads of sH / sW4 complete before either is reused
}

__global__ void __launch_bounds__(NTHREADS, 1)
FusionNeRF_kernel(const float* __restrict__ pts, const float* __restrict__ dir,
                  const float* __restrict__ zv,  const float* __restrict__ tim,
                  MLPParams st, MLPParams dy, float* __restrict__ out, int R)
{
    extern __shared__ float sm[];
    float* sX    = sm + SX_OFF;
    float* sH    = sm + SH_OFF;
    float* sW    = sm + SW_OFF;
    float* sW4   = sm + SW4_OFF;
    float* sOutS = sm + SOUTS_OFF;
    float* sSig  = sm + SSIG_OFF;
    float* sBW   = sm + SBW_OFF;
    float* sRgb  = sm + SRGB_OFF;
    float* sZ    = sm + SZ_OFF;
    float* sWgt  = sm + SWGT_OFF;

    const int tid = threadIdx.x;
    const int ray = blockIdx.x;

    // ---- Phase 1: positional encodings into sX[m][0..98] ----
    if (tid < SS) {
        const int m = tid;
        const long base = (long)ray * SS + m;
        const float p0 = pts[base * 3 + 0], p1 = pts[base * 3 + 1], p2 = pts[base * 3 + 2];
        const float d0 = dir[base * 3 + 0], d1 = dir[base * 3 + 1], d2 = dir[base * 3 + 2];
        const float t  = tim[base];
        sZ[m] = zv[base];

        float* x = sX + m * XPAD;
        x[0] = p0; x[1] = p1; x[2] = p2;
        float f = 1.f; int o = 3;
#pragma unroll
        for (int l = 0; l < 10; l++) {
            float s0, c0, s1, c1, s2, c2;
            sincosf(f * p0, &s0, &c0); sincosf(f * p1, &s1, &c1); sincosf(f * p2, &s2, &c2);
            x[o] = s0; x[o + 1] = s1; x[o + 2] = s2;
            x[o + 3] = c0; x[o + 4] = c1; x[o + 5] = c2;
            o += 6; f *= 2.f;
        }
        x[63] = d0; x[64] = d1; x[65] = d2;
        f = 1.f; o = 66;
#pragma unroll
        for (int l = 0; l < 4; l++) {
            float s0, c0, s1, c1, s2, c2;
            sincosf(f * d0, &s0, &c0); sincosf(f * d1, &s1, &c1); sincosf(f * d2, &s2, &c2);
            x[o] = s0; x[o + 1] = s1; x[o + 2] = s2;
            x[o + 3] = c0; x[o + 4] = c1; x[o + 5] = c2;
            o += 6; f *= 2.f;
        }
        x[90] = t;
        f = 1.f; o = 91;
#pragma unroll
        for (int l = 0; l < 4; l++) {
            float s, c;
            sincosf(f * t, &s, &c);
            x[o] = s; x[o + 1] = c;
            o += 2; f *= 2.f;
        }
        x[99] = 0.f;  // pad col (masked by zeroed W row anyway)
    }
    __syncthreads();

    // ---- Phase 2: static MLP (K=90, padded to 92) ----
    run_mlp4(st.W, st.b, sX, 92, 90, sH, sW);
    {
        float o4[4];
        final_layer<4>(sH, st.W[4], st.b[4], sW4, o4);
        if (tid < SS) {
            sOutS[tid * 4 + 0] = o4[0]; sOutS[tid * 4 + 1] = o4[1];
            sOutS[tid * 4 + 2] = o4[2]; sOutS[tid * 4 + 3] = o4[3];
        }
    }

    // ---- Phase 3: dynamic MLP (K=99, padded to 100) ----
    run_mlp4(dy.W, dy.b, sX, 100, 99, sH, sW);
    {
        float o5[5];
        final_layer<5>(sH, dy.W[4], dy.b[4], sW4, o5);
        if (tid < SS) {
            const int m = tid;
            const float bw = sigmoidf_(o5[4]);
            const float ss = sOutS[m * 4 + 0];
            sSig[m] = (1.f - bw) * ss + bw * o5[0];
            sBW[m]  = bw;
#pragma unroll
            for (int c = 0; c < 3; c++) {
                const float rs = sigmoidf_(sOutS[m * 4 + 1 + c]);
                const float rd = sigmoidf_(o5[1 + c]);
                sRgb[m * 3 + c] = (1.f - bw) * rs + bw * rd;
            }
        }
    }
    __syncthreads();

    // ---- Phase 4: transmittance scan + ray reductions (serial, ~3k cyc, negligible) ----
    if (tid == 0) {
        float T = 1.f, r0 = 0.f, r1 = 0.f, r2 = 0.f, dep = 0.f;
        for (int m = 0; m < SS; m++) {
            const float z = sZ[m];
            const float delta = (m < SS - 1) ? (sZ[m + 1] - z) : 1e10f;
            const float alpha = 1.f - expf(-sSig[m] * delta);
            const float w = alpha * T;
            T *= (1.f - alpha + 1e-10f);
            sWgt[m] = w;
            r0 += w * sRgb[m * 3 + 0];
            r1 += w * sRgb[m * 3 + 1];
            r2 += w * sRgb[m * 3 + 2];
            dep += w * z;
        }
        out[ray * 3 + 0] = r0;
        out[ray * 3 + 1] = r1;
        out[ray * 3 + 2] = r2;
        out[(long)R * 3 + ray] = dep;
    }
    __syncthreads();

    // ---- Phase 5: per-sample weight outputs ----
    if (tid < SS) {
        const int m = tid;
        const float w  = sWgt[m];
        const float bw = sBW[m];
        const long o = (long)ray * SS + m;
        const long base = (long)R * 4;       // after rgb_map (3R) + depth_map (R)
        const long rs = (long)R * SS;
        out[base + o]          = w;
        out[base + rs + o]     = (1.f - bw) * w;
        out[base + 2 * rs + o] = bw * w;
    }
}

extern "C" void kernel_launch(void* const* d_in, const int* in_sizes, int n_in,
                              void* d_out, int out_size)
{
    const float* pts = (const float*)d_in[0];
    const float* dir = (const float*)d_in[1];
    const float* zv  = (const float*)d_in[2];
    const float* tim = (const float*)d_in[3];

    MLPParams st, dy;
    for (int i = 0; i < 5; i++) {
        st.W[i] = (const float*)d_in[4 + 4 * i];
        st.b[i] = (const float*)d_in[5 + 4 * i];
        dy.W[i] = (const float*)d_in[6 + 4 * i];
        dy.b[i] = (const float*)d_in[7 + 4 * i];
    }

    const int R = in_sizes[2] / SS;   // z_vals is [R, S]
    const size_t smem = SMEM_FLOATS * sizeof(float);

    cudaFuncSetAttribute(FusionNeRF_kernel,
                         cudaFuncAttributeMaxDynamicSharedMemorySize, (int)smem);

    FusionNeRF_kernel<<<R, NTHREADS, smem>>>(pts, dir, zv, tim, st, dy, (float*)d_out, R);
}

// round 8
// speedup vs baseline: 2.3749x; 2.3749x over previous
#include <cuda_runtime.h>
#include <cuda_bf16.h>
#include <math.h>
#include <stdint.h>

// ---------------- problem constants ----------------
#define SS        128
#define HID       256
#define NTHREADS  512
#define KC        32               // K per weight chunk (bf16)
#define NCHUNK    28               // per MLP: layer0: 4 (Kpad=128), layers1-3: 8 each
#define ASTRIDE   264              // A plane row stride in bf16 (conflict-free ldmatrix)
#define HSTRIDE   260              // fp32 overlay row stride
#define BSTRIDE   40               // B chunk row stride in bf16 (80B, conflict-free)

// ---- shared memory byte offsets ----
#define A_HI      0                              // 128*264*2 = 67584
#define A_LO      67584                          // 67584            -> 135168
#define BUF0      135168                         // 2 bufs * 2 planes * 20480 = 81920 -> 217088
#define BPLANE    20480
#define BBUFSZ    40960
#define SM_W4     217088                         // 256*5*4 = 5120   -> 222208
#define SM_BIAS   222208                         // 256*4 = 1024     -> 223232
#define SM_OUTS   223232                         // 128*4*4 = 2048   -> 225280
#define SM_SIG    225280                         // 512
#define SM_BW     225792                         // 512
#define SM_RGB    226304                         // 1536
#define SM_Z      227840                         // 512
#define SM_WGT    228352                         // 512 -> 228864
#define SM_TOTAL  228864
// encode scratch (fp32 [128][100] = 51200B) overlays BUF0 between MLPs

// Pre-transposed bf16 hi/lo weight chunk images: [mlp][chunk][plane][256*32]
__device__ __align__(16) __nv_bfloat16 g_wimg[2][NCHUNK][2][HID * KC];

struct MLPParams { const float* W[5]; const float* b[5]; };

// ---------------- PTX helpers (all baseline sm_80 ISA) ----------------
__device__ __forceinline__ uint32_t smem_u32(const void* p) {
    uint32_t a;
    asm("{ .reg .u64 t; cvta.to.shared.u64 t, %1; cvt.u32.u64 %0, t; }" : "=r"(a) : "l"(p));
    return a;
}

#define LDSM4(r0, r1, r2, r3, addr) \
    asm volatile("ldmatrix.sync.aligned.m8n8.x4.shared.b16 {%0,%1,%2,%3}, [%4];" \
        : "=r"(r0), "=r"(r1), "=r"(r2), "=r"(r3) : "r"(addr))

#define MMA16816(c, a0, a1, a2, a3, b0, b1) \
    asm volatile("mma.sync.aligned.m16n8k16.row.col.f32.bf16.bf16.f32 " \
        "{%0,%1,%2,%3}, {%4,%5,%6,%7}, {%8,%9}, {%0,%1,%2,%3};" \
        : "+f"((c)[0]), "+f"((c)[1]), "+f"((c)[2]), "+f"((c)[3]) \
        : "r"(a0), "r"(a1), "r"(a2), "r"(a3), "r"(b0), "r"(b1))

__device__ __forceinline__ void cp16(uint32_t dst, const void* src) {
    asm volatile("cp.async.cg.shared.global [%0], [%1], 16;" :: "r"(dst), "l"(src));
}
#define CP_COMMIT() asm volatile("cp.async.commit_group;" ::: "memory")
#define CP_WAIT1()  asm volatile("cp.async.wait_group 1;" ::: "memory")
#define CP_WAIT0()  asm volatile("cp.async.wait_group 0;" ::: "memory")

__device__ __forceinline__ float sigmoidf_(float x) { return 1.0f / (1.0f + expf(-x)); }

__device__ __forceinline__ void split_pack(float v0, float v1, uint32_t& phi, uint32_t& plo) {
    __nv_bfloat16 h0 = __float2bfloat16(v0);
    __nv_bfloat16 h1 = __float2bfloat16(v1);
    __nv_bfloat16 l0 = __float2bfloat16(v0 - __bfloat162float(h0));
    __nv_bfloat16 l1 = __float2bfloat16(v1 - __bfloat162float(h1));
    phi = (uint32_t)__bfloat16_as_ushort(h0) | ((uint32_t)__bfloat16_as_ushort(h1) << 16);
    plo = (uint32_t)__bfloat16_as_ushort(l0) | ((uint32_t)__bfloat16_as_ushort(l1) << 16);
}

// ---------------- pre-pass: build [N][Kc] bf16 hi/lo chunk images ----------------
__global__ void prepass_kernel(MLPParams st, MLPParams dy) {
    const int bi  = blockIdx.x;          // 0..55
    const int mlp = bi / NCHUNK;
    const int c   = bi % NCHUNK;
    const int layer = (c < 4) ? 0 : 1 + (c - 4) / 8;
    const int kbase = (c < 4) ? c * KC : ((c - 4) % 8) * KC;
    const float* W = mlp ? dy.W[layer] : st.W[layer];
    const int Kreal = (layer == 0) ? (mlp ? 99 : 90) : HID;

    __nv_bfloat16* outH = g_wimg[mlp][c][0];
    __nv_bfloat16* outL = g_wimg[mlp][c][1];
    const int n = threadIdx.x;           // 0..255
    for (int k = 0; k < KC; k++) {
        const int kg = kbase + k;
        const float w = (kg < Kreal) ? __ldg(W + (size_t)kg * HID + n) : 0.f;
        __nv_bfloat16 h = __float2bfloat16(w);
        __nv_bfloat16 l = __float2bfloat16(w - __bfloat162float(h));
        outH[n * KC + k] = h;
        outL[n * KC + k] = l;
    }
}

// ---------------- GEMM chunk: 16 warps, warp tile 16(M) x 128(N), Kc=32 ----------------
__device__ __forceinline__ void gemm_chunk(uint32_t aHi, uint32_t aLo, uint32_t bB,
                                           float acc[16][4]) {
#pragma unroll
    for (int ks = 0; ks < 2; ks++) {
        uint32_t ah0, ah1, ah2, ah3, al0, al1, al2, al3;
        LDSM4(ah0, ah1, ah2, ah3, aHi + ks * 32);
        LDSM4(al0, al1, al2, al3, aLo + ks * 32);
        const uint32_t bk = bB + ks * 32;
#pragma unroll
        for (int p = 0; p < 8; p++) {
            uint32_t bh0, bh1, bh2, bh3, bl0, bl1, bl2, bl3;
            LDSM4(bh0, bh1, bh2, bh3, bk + p * (16 * BSTRIDE * 2));
            LDSM4(bl0, bl1, bl2, bl3, bk + BPLANE + p * (16 * BSTRIDE * 2));
            MMA16816(acc[2 * p],     ah0, ah1, ah2, ah3, bh0, bh1);
            MMA16816(acc[2 * p + 1], ah0, ah1, ah2, ah3, bh2, bh3);
            MMA16816(acc[2 * p],     ah0, ah1, ah2, ah3, bl0, bl1);
            MMA16816(acc[2 * p + 1], ah0, ah1, ah2, ah3, bl2, bl3);
            MMA16816(acc[2 * p],     al0, al1, al2, al3, bh0, bh1);
            MMA16816(acc[2 * p + 1], al0, al1, al2, al3, bh2, bh3);
        }
    }
}

// ---------------- main kernel ----------------
__global__ void __launch_bounds__(NTHREADS, 1)
nerf_main(const float* __restrict__ pts, const float* __restrict__ dir,
          const float* __restrict__ zv,  const float* __restrict__ tim,
          MLPParams st, MLPParams dy, float* __restrict__ out, int R)
{
    extern __shared__ char sm[];
    const uint32_t sbase = smem_u32(sm);

    const int tid  = threadIdx.x;
    const int wid  = tid >> 5;
    const int lane = tid & 31;
    const int ray  = blockIdx.x;

    const int mi = wid >> 1;             // 0..7  -> rows 16*mi
    const int nj = wid & 1;              // 0..1  -> cols 128*nj

    float* sZ    = (float*)(sm + SM_Z);
    float* sWgt  = (float*)(sm + SM_WGT);
    float* sSig  = (float*)(sm + SM_SIG);
    float* sBW   = (float*)(sm + SM_BW);
    float* sRgb  = (float*)(sm + SM_RGB);
    float* sOutS = (float*)(sm + SM_OUTS);
    float* sBias = (float*)(sm + SM_BIAS);
    float* sW4f  = (float*)(sm + SM_W4);
    float* sHf   = (float*)(sm + A_HI);      // fp32 overlay, stride HSTRIDE

    if (tid < SS) sZ[tid] = zv[(long)ray * SS + tid];

    // per-thread ldmatrix address components
    const int r8 = lane & 7, g = lane >> 3;
    const uint32_t aRow = (uint32_t)(16 * mi + (g & 1) * 8 + r8);
    const uint32_t aColOff = (uint32_t)((g >> 1) * 8);
    const uint32_t aHiBase = sbase + A_HI + (aRow * ASTRIDE + aColOff) * 2;
    const uint32_t aLoBase = sbase + A_LO + (aRow * ASTRIDE + aColOff) * 2;
    const uint32_t bRow = (uint32_t)(nj * 128 + (g >> 1) * 8 + r8);
    const uint32_t bOff = (bRow * BSTRIDE + (g & 1) * 8) * 2;

    const int rowTop = 16 * mi + (lane >> 2);
    const int colB   = nj * 128 + 2 * (lane & 3);

    for (int mlp = 0; mlp < 2; mlp++) {
        const float* const* Wp = mlp ? dy.W : st.W;
        const float* const* Bp = mlp ? dy.b : st.b;
        const int n4 = mlp ? 5 : 4;

        // ---- encode into fp32 scratch (overlays B buffers; all cp.async retired) ----
        CP_WAIT0();
        __syncthreads();
        float* scratch = (float*)(sm + BUF0);
        if (tid < SS) {
            const int m = tid;
            const long base = (long)ray * SS + m;
            const float p0 = pts[base*3+0], p1 = pts[base*3+1], p2 = pts[base*3+2];
            const float d0 = dir[base*3+0], d1 = dir[base*3+1], d2 = dir[base*3+2];
            const float t  = tim[base];
            float* x = scratch + m * 100;
            x[0] = p0; x[1] = p1; x[2] = p2;
            float f = 1.f; int o = 3;
#pragma unroll
            for (int l = 0; l < 10; l++) {
                float s0,c0,s1,c1,s2,c2;
                sincosf(f*p0,&s0,&c0); sincosf(f*p1,&s1,&c1); sincosf(f*p2,&s2,&c2);
                x[o]=s0; x[o+1]=s1; x[o+2]=s2; x[o+3]=c0; x[o+4]=c1; x[o+5]=c2;
                o += 6; f *= 2.f;
            }
            x[63]=d0; x[64]=d1; x[65]=d2;
            f = 1.f; o = 66;
#pragma unroll
            for (int l = 0; l < 4; l++) {
                float s0,c0,s1,c1,s2,c2;
                sincosf(f*d0,&s0,&c0); sincosf(f*d1,&s1,&c1); sincosf(f*d2,&s2,&c2);
                x[o]=s0; x[o+1]=s1; x[o+2]=s2; x[o+3]=c0; x[o+4]=c1; x[o+5]=c2;
                o += 6; f *= 2.f;
            }
            x[90]=t;
            f = 1.f; o = 91;
#pragma unroll
            for (int l = 0; l < 4; l++) {
                float s, c; sincosf(f*t, &s, &c);
                x[o]=s; x[o+1]=c; o += 2; f *= 2.f;
            }
        }
        __syncthreads();

        // ---- pack encodings to A planes (bf16 hi/lo), cols 0..127 (zero pad >=100) ----
        {
            const int m  = tid >> 2;
            const int j0 = (tid & 3) * 16;
            const float* xr = scratch + m * 100;
            uint32_t* aH = (uint32_t*)(sm + A_HI);
            uint32_t* aL = (uint32_t*)(sm + A_LO);
#pragma unroll
            for (int j = 0; j < 16; j++) {
                const int k0 = 2 * (j0 + j);
                const float v0 = (k0     < 100) ? xr[k0]     : 0.f;
                const float v1 = (k0 + 1 < 100) ? xr[k0 + 1] : 0.f;
                uint32_t phi, plo;
                split_pack(v0, v1, phi, plo);
                aH[m * (ASTRIDE/2) + j0 + j] = phi;
                aL[m * (ASTRIDE/2) + j0 + j] = plo;
            }
        }
        __syncthreads();

        // ---- prefetch chunks 0,1 ----
        int cg = 0;
        {
            for (int pc = 0; pc < 2; pc++) {
                const char* srcH = (const char*)g_wimg[mlp][pc][0];
                const char* srcL = (const char*)g_wimg[mlp][pc][1];
                const uint32_t dstB = sbase + BUF0 + pc * BBUFSZ;
#pragma unroll
                for (int i = 0; i < 2; i++) {
                    const int idx = tid + i * NTHREADS;         // 0..1023
                    const uint32_t d = dstB + (uint32_t)(idx >> 2) * (BSTRIDE*2) + (idx & 3) * 16;
                    cp16(d,          srcH + idx * 16);
                    cp16(d + BPLANE, srcL + idx * 16);
                }
                CP_COMMIT();
            }
        }

        for (int layer = 0; layer < 4; layer++) {
            // stage bias (+ final W4) for this layer
            for (int i = tid; i < HID; i += NTHREADS) sBias[i] = __ldg(Bp[layer] + i);
            if (layer == 3)
                for (int i = tid; i < HID * n4; i += NTHREADS) sW4f[i] = __ldg(Wp[4] + i);

            float acc[16][4];
#pragma unroll
            for (int a = 0; a < 16; a++)
#pragma unroll
                for (int q = 0; q < 4; q++) acc[a][q] = 0.f;

            const int nch = (layer == 0) ? 4 : 8;
            for (int c = 0; c < nch; c++) {
                CP_WAIT1();                       // chunk cg resident
                __syncthreads();
                const uint32_t bB = sbase + BUF0 + (uint32_t)(cg & 1) * BBUFSZ + bOff;
                gemm_chunk(aHiBase + c * (KC * 2), aLoBase + c * (KC * 2), bB, acc);
                __syncthreads();
                // prefetch chunk cg+2 into buf (cg&1); always commit to keep group count uniform
                if (cg + 2 < NCHUNK) {
                    const int nc = cg + 2;
                    const char* srcH = (const char*)g_wimg[mlp][nc][0];
                    const char* srcL = (const char*)g_wimg[mlp][nc][1];
                    const uint32_t dstB = sbase + BUF0 + (uint32_t)(cg & 1) * BBUFSZ;
#pragma unroll
                    for (int i = 0; i < 2; i++) {
                        const int idx = tid + i * NTHREADS;
                        const uint32_t d = dstB + (uint32_t)(idx >> 2) * (BSTRIDE*2) + (idx & 3) * 16;
                        cp16(d,          srcH + idx * 16);
                        cp16(d + BPLANE, srcL + idx * 16);
                    }
                }
                CP_COMMIT();
                cg++;
            }

            // ---- epilogue ----
            if (layer < 3) {
                uint32_t* aH = (uint32_t*)(sm + A_HI);
                uint32_t* aL = (uint32_t*)(sm + A_LO);
#pragma unroll
                for (int nb = 0; nb < 16; nb++) {
                    const int col = colB + nb * 8;
                    const float b0 = sBias[col], b1 = sBias[col + 1];
                    const float h00 = fmaxf(acc[nb][0] + b0, 0.f);
                    const float h01 = fmaxf(acc[nb][1] + b1, 0.f);
                    const float h10 = fmaxf(acc[nb][2] + b0, 0.f);
                    const float h11 = fmaxf(acc[nb][3] + b1, 0.f);
                    uint32_t phi, plo;
                    split_pack(h00, h01, phi, plo);
                    aH[rowTop * (ASTRIDE/2) + (col >> 1)] = phi;
                    aL[rowTop * (ASTRIDE/2) + (col >> 1)] = plo;
                    split_pack(h10, h11, phi, plo);
                    aH[(rowTop + 8) * (ASTRIDE/2) + (col >> 1)] = phi;
                    aL[(rowTop + 8) * (ASTRIDE/2) + (col >> 1)] = plo;
                }
            } else {
                // fp32 relu output into overlay (A planes fully consumed)
#pragma unroll
                for (int nb = 0; nb < 16; nb++) {
                    const int col = colB + nb * 8;
                    const float b0 = sBias[col], b1 = sBias[col + 1];
                    sHf[rowTop * HSTRIDE + col]           = fmaxf(acc[nb][0] + b0, 0.f);
                    sHf[rowTop * HSTRIDE + col + 1]       = fmaxf(acc[nb][1] + b1, 0.f);
                    sHf[(rowTop + 8) * HSTRIDE + col]     = fmaxf(acc[nb][2] + b0, 0.f);
                    sHf[(rowTop + 8) * HSTRIDE + col + 1] = fmaxf(acc[nb][3] + b1, 0.f);
                }
            }
            __syncthreads();
        }

        // ---- final 256 -> n4 dot per sample ----
        if (tid < SS) {
            float o5[5];
            const float* b4 = Bp[4];
#pragma unroll
            for (int j = 0; j < 5; j++) o5[j] = (j < n4) ? __ldg(b4 + j) : 0.f;
            const float* arow = sHf + tid * HSTRIDE;
            for (int k = 0; k < HID; k += 4) {
                const float4 a = *reinterpret_cast<const float4*>(arow + k);
#pragma unroll
                for (int kk = 0; kk < 4; kk++) {
                    const float av = (kk == 0) ? a.x : (kk == 1) ? a.y : (kk == 2) ? a.z : a.w;
#pragma unroll
                    for (int j = 0; j < 5; j++)
                        if (j < n4) o5[j] += av * sW4f[(k + kk) * n4 + j];
                }
            }
            const int m = tid;
            if (mlp == 0) {
                sOutS[m*4+0] = o5[0]; sOutS[m*4+1] = o5[1];
                sOutS[m*4+2] = o5[2]; sOutS[m*4+3] = o5[3];
            } else {
                const float bw = sigmoidf_(o5[4]);
                sSig[m] = (1.f - bw) * sOutS[m*4+0] + bw * o5[0];
                sBW[m]  = bw;
#pragma unroll
                for (int cc = 0; cc < 3; cc++) {
                    const float rs = sigmoidf_(sOutS[m*4+1+cc]);
                    const float rd = sigmoidf_(o5[1+cc]);
                    sRgb[m*3+cc] = (1.f - bw) * rs + bw * rd;
                }
            }
        }
        __syncthreads();
    }

    // ---- transmittance scan + ray reductions ----
    if (tid == 0) {
        float T = 1.f, r0 = 0.f, r1 = 0.f, r2 = 0.f, dep = 0.f;
        for (int m = 0; m < SS; m++) {
            const float z = sZ[m];
            const float delta = (m < SS - 1) ? (sZ[m + 1] - z) : 1e10f;
            const float alpha = 1.f - expf(-sSig[m] * delta);
            const float w = alpha * T;
            T *= (1.f - alpha + 1e-10f);
            sWgt[m] = w;
            r0 += w * sRgb[m*3+0];
            r1 += w * sRgb[m*3+1];
            r2 += w * sRgb[m*3+2];
            dep += w * z;
        }
        out[ray*3+0] = r0; out[ray*3+1] = r1; out[ray*3+2] = r2;
        out[(long)R * 3 + ray] = dep;
    }
    __syncthreads();

    if (tid < SS) {
        const int m = tid;
        const float w  = sWgt[m];
        const float bw = sBW[m];
        const long o = (long)ray * SS + m;
        const long base = (long)R * 4;
        const long rs = (long)R * SS;
        out[base + o]          = w;
        out[base + rs + o]     = (1.f - bw) * w;
        out[base + 2 * rs + o] = bw * w;
    }
}

extern "C" void kernel_launch(void* const* d_in, const int* in_sizes, int n_in,
                              void* d_out, int out_size)
{
    const float* pts = (const float*)d_in[0];
    const float* dir = (const float*)d_in[1];
    const float* zv  = (const float*)d_in[2];
    const float* tim = (const float*)d_in[3];

    MLPParams st, dy;
    for (int i = 0; i < 5; i++) {
        st.W[i] = (const float*)d_in[4 + 4 * i];
        st.b[i] = (const float*)d_in[5 + 4 * i];
        dy.W[i] = (const float*)d_in[6 + 4 * i];
        dy.b[i] = (const float*)d_in[7 + 4 * i];
    }

    const int R = in_sizes[2] / SS;

    prepass_kernel<<<2 * NCHUNK, 256>>>(st, dy);

    cudaFuncSetAttribute(nerf_main, cudaFuncAttributeMaxDynamicSharedMemorySize, SM_TOTAL);
    nerf_main<<<R, NTHREADS, SM_TOTAL>>>(pts, dir, zv, tim, st, dy, (float*)d_out, R);
}